// round 15
// baseline (speedup 1.0000x reference)
#include <cuda_runtime.h>
#include <cstdint>
#include <cstddef>

// ---------------- problem constants ----------------
#define NB 4
#define NT 2048
#define NM 1024
#define NH 2048
#define NE 8
#define NS (NB * NT)       // 8192 tokens
#define NC 2048            // expert capacity

// GEMM tiling (int8 path)
#define BM 128             // tokens per CTA
#define BN 128             // h cols per CTA
#define BKT 64             // K elems (bytes) per stage
#define NKT (NM / BKT)     // 16 stages
// smem stage: X1a | X2a | W1b | W2b, rows padded to 80B (64 s8 + 16 pad)
#define ROWB 80
#define OFF_A2 10240       // 128*80
#define OFF_B1 20480
#define OFF_B2 30720
#define STAGE  40960
#define SMEM_DYN (2 * STAGE)

// ---------------- device scratch (no allocs allowed) ----------------
__device__ int   g_topi[NS * 2];
__device__ float g_gate[NS * 2];
__device__ int   g_tok[NE * NC];
__device__ float g_gts[NE * NC];
__device__ int   g_ne[NE];
__device__ __align__(16) float g_w2s[NE * NH];
__device__ float g_b2s[NE];
__device__ float g_osum[NS];
__device__ float g_q1[NS];                         // per-token quant step
__device__ __align__(16) float g_p1[NE * NH];      // per-(e,h) quant step
__device__ __align__(16) signed char g_x1[(size_t)NS * NM];
__device__ __align__(16) signed char g_x2[(size_t)NS * NM];
__device__ __align__(16) signed char g_w1q1[(size_t)NE * NH * NM];  // [e][h][m]
__device__ __align__(16) signed char g_w1q2[(size_t)NE * NH * NM];

// ---------------- helpers ----------------
__device__ __forceinline__ uint32_t smem_u32(const void* p) {
    uint32_t a;
    asm("{ .reg .u64 t; cvta.to.shared.u64 t, %1; cvt.u32.u64 %0, t; }"
        : "=r"(a) : "l"(p));
    return a;
}
__device__ __forceinline__ void cp16(uint32_t dst, const void* src) {
    asm volatile("cp.async.cg.shared.global [%0], [%1], 16;"
                 :: "r"(dst), "l"(src));
}
__device__ __forceinline__ void cp_commit() {
    asm volatile("cp.async.commit_group;" ::: "memory");
}
__device__ __forceinline__ void cp_wait1() {
    asm volatile("cp.async.wait_group 1;" ::: "memory");
}
__device__ __forceinline__ void cp_wait0() {
    asm volatile("cp.async.wait_group 0;" ::: "memory");
}
__device__ __forceinline__ uint32_t ld32s(const char* p) {
    return *reinterpret_cast<const uint32_t*>(p);
}
// m16n8k32 s8 IMMA (sm_80 PTX; legacy path on sm_103): 4096 MAC/instr, exact int32 acc
__device__ __forceinline__ void mma_s8(int* d, const uint32_t* a, const uint32_t* b) {
    asm volatile(
        "mma.sync.aligned.m16n8k32.row.col.s32.s8.s8.s32 "
        "{%0,%1,%2,%3}, {%4,%5,%6,%7}, {%8,%9}, {%0,%1,%2,%3};\n"
        : "+r"(d[0]), "+r"(d[1]), "+r"(d[2]), "+r"(d[3])
        : "r"(a[0]), "r"(a[1]), "r"(a[2]), "r"(a[3]), "r"(b[0]), "r"(b[1]));
}
__device__ __forceinline__ int q8(float v) {
    int i = __float2int_rn(v);
    return i > 127 ? 127 : (i < -127 ? -127 : i);
}
__device__ __forceinline__ uint32_t pack4(int a, int b, int c, int d) {
    return (uint32_t)(a & 0xff) | ((uint32_t)(b & 0xff) << 8) |
           ((uint32_t)(c & 0xff) << 16) | ((uint32_t)(d & 0xff) << 24);
}

// ---------------- router + x quantization (single x pass) ----------------
// grid NS blocks x 256 threads; thread handles m = tid*4..tid*4+3
__global__ void router_quant(const float* __restrict__ x, const float* __restrict__ wg) {
    int s = blockIdx.x;
    int tid = threadIdx.x;
    float4 xv = *reinterpret_cast<const float4*>(x + (size_t)s * NM + tid * 4);
    float vv[4] = {xv.x, xv.y, xv.z, xv.w};

    float acc[8];
    #pragma unroll
    for (int e = 0; e < 8; ++e) acc[e] = 0.f;
    float mxa = 0.f;
    #pragma unroll
    for (int j = 0; j < 4; ++j) {
        float xm = vv[j];
        mxa = fmaxf(mxa, fabsf(xm));
        const float4* w4 = reinterpret_cast<const float4*>(wg + (size_t)(tid * 4 + j) * NE);
        float4 wa = w4[0], wb = w4[1];
        acc[0] += xm * wa.x; acc[1] += xm * wa.y; acc[2] += xm * wa.z; acc[3] += xm * wa.w;
        acc[4] += xm * wb.x; acc[5] += xm * wb.y; acc[6] += xm * wb.z; acc[7] += xm * wb.w;
    }
    #pragma unroll
    for (int off = 16; off; off >>= 1) {
        #pragma unroll
        for (int e = 0; e < 8; ++e) acc[e] += __shfl_xor_sync(0xffffffffu, acc[e], off);
        mxa = fmaxf(mxa, __shfl_xor_sync(0xffffffffu, mxa, off));
    }
    __shared__ float wsum[8][8];
    __shared__ float wmax[8];
    __shared__ float s_step;
    int lane = tid & 31, w = tid >> 5;
    if (lane == 0) {
        #pragma unroll
        for (int e = 0; e < 8; ++e) wsum[w][e] = acc[e];
        wmax[w] = mxa;
    }
    __syncthreads();
    if (tid == 0) {
        float l[8];
        float mall = 0.f;
        #pragma unroll
        for (int e = 0; e < 8; ++e) {
            float t = 0.f;
            #pragma unroll
            for (int ww = 0; ww < 8; ++ww) t += wsum[ww][e];
            l[e] = t;
        }
        #pragma unroll
        for (int ww = 0; ww < 8; ++ww) mall = fmaxf(mall, wmax[ww]);
        float step = fmaxf(mall, 1e-30f) / 127.f;
        s_step = step;
        g_q1[s] = step;

        float mx = l[0];
        #pragma unroll
        for (int e = 1; e < 8; ++e) mx = fmaxf(mx, l[e]);
        float p[8], Z = 0.f;
        #pragma unroll
        for (int e = 0; e < 8; ++e) { p[e] = expf(l[e] - mx); Z += p[e]; }
        int i0 = 0;
        #pragma unroll
        for (int e = 1; e < 8; ++e) if (l[e] > l[i0]) i0 = e;
        int i1 = (i0 == 0) ? 1 : 0;
        #pragma unroll
        for (int e = 0; e < 8; ++e) if (e != i0 && l[e] > l[i1]) i1 = e;
        float s0 = p[i0] / Z, s1 = p[i1] / Z;
        float denom = s0 + s1 + 1e-9f;
        g_topi[s * 2 + 0] = i0;
        g_topi[s * 2 + 1] = i1;
        g_gate[s * 2 + 0] = s0 / denom;
        g_gate[s * 2 + 1] = s1 / denom;
        g_osum[s] = 0.f;
    }
    __syncthreads();
    float step = s_step;
    float inv = 1.f / step;
    int x1i[4], x2i[4];
    #pragma unroll
    for (int j = 0; j < 4; ++j) {
        x1i[j] = q8(vv[j] * inv);
        float r = vv[j] - (float)x1i[j] * step;
        x2i[j] = q8(r * 256.f * inv);
    }
    size_t o4 = (size_t)s * NM + tid * 4;
    *reinterpret_cast<uint32_t*>(g_x1 + o4) = pack4(x1i[0], x1i[1], x1i[2], x1i[3]);
    *reinterpret_cast<uint32_t*>(g_x2 + o4) = pack4(x2i[0], x2i[1], x2i[2], x2i[3]);
}

// ---------------- w1 column max: p1[e][h] = max_m |w1[e][m][h]| / 127 ----------------
__global__ void colmax_w1(const float* __restrict__ w1) {
    int e = blockIdx.y;
    int h = blockIdx.x * 256 + threadIdx.x;
    const float* p = w1 + (size_t)e * NM * NH + h;
    float mx = 0.f;
    #pragma unroll 4
    for (int m = 0; m < NM; ++m) mx = fmaxf(mx, fabsf(p[(size_t)m * NH]));
    g_p1[e * NH + h] = fmaxf(mx, 1e-30f) / 127.f;
}

// ---------------- w1 transpose + quant: [e][m][h] -> s8 planes [e][h][m] ----------------
__global__ void transpose_quant_w1(const float* __restrict__ w1) {
    __shared__ float tile[32][33];
    int e = blockIdx.z;
    int m0 = blockIdx.x * 32, h0 = blockIdx.y * 32;
    const float* src = w1 + (size_t)e * NM * NH;
    int tx = threadIdx.x, ty = threadIdx.y;
    int tid = ty * 32 + tx;
    #pragma unroll
    for (int i = 0; i < 32; i += 8)
        tile[ty + i][tx] = src[(size_t)(m0 + ty + i) * NH + h0 + tx];
    __syncthreads();
    int hrow = tid >> 3;       // 0..31
    int mg = tid & 7;          // 0..7, 4 m each
    float step = g_p1[e * NH + h0 + hrow];
    float inv = 1.f / step;
    int w1i[4], w2i[4];
    #pragma unroll
    for (int j = 0; j < 4; ++j) {
        float v = tile[mg * 4 + j][hrow];
        w1i[j] = q8(v * inv);
        float r = v - (float)w1i[j] * step;
        w2i[j] = q8(r * 256.f * inv);
    }
    size_t di = (size_t)e * NH * NM + (size_t)(h0 + hrow) * NM + m0 + mg * 4;
    *reinterpret_cast<uint32_t*>(g_w1q1 + di) = pack4(w1i[0], w1i[1], w1i[2], w1i[3]);
    *reinterpret_cast<uint32_t*>(g_w1q2 + di) = pack4(w2i[0], w2i[1], w2i[2], w2i[3]);
}

// ---------------- w2 column-sum (+ b2 sum in extra block) ----------------
__global__ void w2b2sum_kernel(const float* __restrict__ w2, const float* __restrict__ b2) {
    int lane = threadIdx.x & 31;
    if ((int)blockIdx.x < NE * NH / 8) {
        int r = blockIdx.x * 8 + (threadIdx.x >> 5);
        const float* p = w2 + (size_t)r * NM;
        float s = 0.f;
        #pragma unroll 4
        for (int m = lane; m < NM; m += 32) s += p[m];
        #pragma unroll
        for (int off = 16; off; off >>= 1) s += __shfl_xor_sync(0xffffffffu, s, off);
        if (lane == 0) g_w2s[r] = s;
    } else {
        int e = threadIdx.x >> 5;
        float s = 0.f;
        for (int m = lane; m < NM; m += 32) s += b2[e * NM + m];
        #pragma unroll
        for (int off = 16; off; off >>= 1) s += __shfl_xor_sync(0xffffffffu, s, off);
        if (lane == 0) g_b2s[e] = s;
    }
}

// ---------------- build: ordered rank scan ----------------
__global__ void build_kernel() {
    int e = blockIdx.x;
    int tid = threadIdx.x;
    int lane = tid & 31, wrp = tid >> 5;
    __shared__ int wsum[32];
    int base = 0;
    float b2s = g_b2s[e];
    for (int j = 0; j < 2; ++j) {
        for (int chunk = 0; chunk < NS; chunk += 1024) {
            int s = chunk + tid;
            int f = (g_topi[s * 2 + j] == e) ? 1 : 0;
            unsigned bal = __ballot_sync(0xffffffffu, f);
            int incl_w = __popc(bal & ((2u << lane) - 1u));
            if (lane == 0) wsum[wrp] = __popc(bal);
            __syncthreads();
            if (wrp == 0) {
                int v = wsum[lane];
                #pragma unroll
                for (int off = 1; off < 32; off <<= 1) {
                    int n = __shfl_up_sync(0xffffffffu, v, off);
                    if (lane >= off) v += n;
                }
                wsum[lane] = v;
            }
            __syncthreads();
            int prev = wrp ? wsum[wrp - 1] : 0;
            int incl = prev + incl_w;
            int total = wsum[31];
            if (f) {
                int pos = base + incl - 1;
                if (pos < NC) {
                    g_tok[e * NC + pos] = s;
                    float g = g_gate[s * 2 + j];
                    g_gts[e * NC + pos] = g;
                    atomicAdd(&g_osum[s], g * b2s);
                }
            }
            base += total;
            __syncthreads();
        }
    }
    int ne = base < NC ? base : NC;
    if (tid == 0) g_ne[e] = ne;
    for (int pos = ne + tid; pos < NC; pos += 1024) {
        g_tok[e * NC + pos] = 0;
        g_gts[e * NC + pos] = 0.f;
    }
}

// ---------------- grouped GEMM: IMMA s8 3-product, fused epilogue ----------------
// grid (NC/BM=16, NH/BN=16, NE=8), 256 threads, 2-stage cp.async pipeline.
// main acc: X1*W1 (weight 1); corr acc: X1*W2 + X2*W1 (weight 1/256). int32 exact.
__global__ __launch_bounds__(256, 1)
void expert_gemm_imma(const float* __restrict__ b1) {
    int e = blockIdx.z;
    int ne = g_ne[e];
    int row0 = blockIdx.x * BM;
    if (row0 >= ne) return;
    int h0 = blockIdx.y * BN;

    extern __shared__ __align__(16) char dsm[];
    __shared__ int   s_tok[BM];
    __shared__ float s_gate[BM];
    __shared__ float s_q1[BM];
    __shared__ float s_p1[BN];
    __shared__ float s_bb[BN], s_ww[BN];
    __shared__ float s_rs[BM];

    int tid = threadIdx.x;
    int lane = tid & 31, warp = tid >> 5;
    int gid = lane >> 2, tig = lane & 3;
    int wm = warp >> 2, wn = warp & 3;   // warp tile: 64 rows x 32 cols

    if (tid < BM) {
        int tok = g_tok[e * NC + row0 + tid];
        s_tok[tid]  = tok;
        s_gate[tid] = g_gts[e * NC + row0 + tid];
        s_q1[tid]   = g_q1[tok];
        s_p1[tid]   = g_p1[e * NH + h0 + tid];
        s_bb[tid]   = b1[(size_t)e * NH + h0 + tid];
        s_ww[tid]   = g_w2s[(size_t)e * NH + h0 + tid];
        s_rs[tid]   = 0.f;
    }
    __syncthreads();

    // loader plan: 16B chunks, 2 per thread per plane (128 rows x 4 chunks = 512)
    size_t offA[2], offB[2];
    uint32_t dAB[2];
    #pragma unroll
    for (int i = 0; i < 2; ++i) {
        int u = tid + 256 * i;
        int row = u >> 2, c = u & 3;
        offA[i] = (size_t)s_tok[row] * NM + c * 16;
        offB[i] = ((size_t)e * NH + h0 + row) * NM + c * 16;
        dAB[i] = row * ROWB + c * 16;
    }
    uint32_t smemU = smem_u32(dsm);

    int accM[4][4][4], accC[4][4][4];
    #pragma unroll
    for (int im = 0; im < 4; ++im)
        #pragma unroll
        for (int in = 0; in < 4; ++in)
            #pragma unroll
            for (int q = 0; q < 4; ++q) { accM[im][in][q] = 0; accC[im][in][q] = 0; }

    // prologue: stage 0
    #pragma unroll
    for (int i = 0; i < 2; ++i) {
        cp16(smemU + dAB[i], g_x1 + offA[i]);
        cp16(smemU + OFF_A2 + dAB[i], g_x2 + offA[i]);
        cp16(smemU + OFF_B1 + dAB[i], g_w1q1 + offB[i]);
        cp16(smemU + OFF_B2 + dAB[i], g_w1q2 + offB[i]);
    }
    cp_commit();

    #pragma unroll 1
    for (int kt = 0; kt < NKT; ++kt) {
        if (kt + 1 < NKT) {
            uint32_t sb = smemU + ((kt + 1) & 1) * STAGE;
            int ko = (kt + 1) * BKT;
            #pragma unroll
            for (int i = 0; i < 2; ++i) {
                cp16(sb + dAB[i], g_x1 + offA[i] + ko);
                cp16(sb + OFF_A2 + dAB[i], g_x2 + offA[i] + ko);
                cp16(sb + OFF_B1 + dAB[i], g_w1q1 + offB[i] + ko);
                cp16(sb + OFF_B2 + dAB[i], g_w1q2 + offB[i] + ko);
            }
            cp_commit();
            cp_wait1();
        } else {
            cp_wait0();
        }
        __syncthreads();

        const char* bp = dsm + (kt & 1) * STAGE;
        const char* A1 = bp;
        const char* A2 = bp + OFF_A2;
        const char* B1 = bp + OFF_B1;
        const char* B2 = bp + OFF_B2;

        #pragma unroll
        for (int ks = 0; ks < 2; ++ks) {
            int kOff = ks * 32 + tig * 4;
            uint32_t b1f[4][2], b2f[4][2];
            #pragma unroll
            for (int in = 0; in < 4; ++in) {
                int rb = (wn * 32 + in * 8 + gid) * ROWB + kOff;
                b1f[in][0] = ld32s(B1 + rb); b1f[in][1] = ld32s(B1 + rb + 16);
                b2f[in][0] = ld32s(B2 + rb); b2f[in][1] = ld32s(B2 + rb + 16);
            }
            #pragma unroll
            for (int im = 0; im < 4; ++im) {
                int ra = (wm * 64 + im * 16 + gid) * ROWB + kOff;
                uint32_t a1[4] = {ld32s(A1 + ra), ld32s(A1 + ra + 8 * ROWB),
                                  ld32s(A1 + ra + 16), ld32s(A1 + ra + 8 * ROWB + 16)};
                uint32_t a2[4] = {ld32s(A2 + ra), ld32s(A2 + ra + 8 * ROWB),
                                  ld32s(A2 + ra + 16), ld32s(A2 + ra + 8 * ROWB + 16)};
                #pragma unroll
                for (int in = 0; in < 4; ++in) mma_s8(accM[im][in], a1, b1f[in]);
                #pragma unroll
                for (int in = 0; in < 4; ++in) mma_s8(accC[im][in], a1, b2f[in]);
                #pragma unroll
                for (int in = 0; in < 4; ++in) mma_s8(accC[im][in], a2, b1f[in]);
            }
        }
        __syncthreads();
    }

    // fused epilogue: dequant, +b1, relu, .w2sum, rowsum, gate scatter
    const float inv256 = 1.f / 256.f;
    #pragma unroll
    for (int im = 0; im < 4; ++im) {
        int r = wm * 64 + im * 16 + gid;
        float qa = s_q1[r], qb = s_q1[r + 8];
        float rs0 = 0.f, rs1 = 0.f;
        #pragma unroll
        for (int in = 0; in < 4; ++in) {
            int col = wn * 32 + in * 8 + 2 * tig;
            float p0 = s_p1[col], p1v = s_p1[col + 1];
            float bb0 = s_bb[col], bb1 = s_bb[col + 1];
            float w0 = s_ww[col], w1v = s_ww[col + 1];
            float v0 = ((float)accM[im][in][0] + (float)accC[im][in][0] * inv256) * (qa * p0);
            float v1 = ((float)accM[im][in][1] + (float)accC[im][in][1] * inv256) * (qa * p1v);
            float v2 = ((float)accM[im][in][2] + (float)accC[im][in][2] * inv256) * (qb * p0);
            float v3 = ((float)accM[im][in][3] + (float)accC[im][in][3] * inv256) * (qb * p1v);
            rs0 += fmaxf(v0 + bb0, 0.f) * w0 + fmaxf(v1 + bb1, 0.f) * w1v;
            rs1 += fmaxf(v2 + bb0, 0.f) * w0 + fmaxf(v3 + bb1, 0.f) * w1v;
        }
        rs0 += __shfl_xor_sync(0xffffffffu, rs0, 1);
        rs0 += __shfl_xor_sync(0xffffffffu, rs0, 2);
        rs1 += __shfl_xor_sync(0xffffffffu, rs1, 1);
        rs1 += __shfl_xor_sync(0xffffffffu, rs1, 2);
        if (tig == 0) {
            atomicAdd(&s_rs[r], rs0);
            atomicAdd(&s_rs[r + 8], rs1);
        }
    }
    __syncthreads();
    if (tid < BM) {
        int r = row0 + tid;
        if (r < ne)
            atomicAdd(&g_osum[s_tok[tid]], s_gate[tid] * s_rs[tid]);
    }
}

// ---------------- per-batch log_softmax over T ----------------
__global__ void logsoftmax_kernel(float* __restrict__ out) {
    int b = blockIdx.x;
    int tid = threadIdx.x;
    int lane = tid & 31, w = tid >> 5;
    const float* row = g_osum + (size_t)b * NT;
    float v0 = row[tid], v1 = row[tid + 1024];
    __shared__ float sm[32];

    float m = fmaxf(v0, v1);
    #pragma unroll
    for (int off = 16; off; off >>= 1) m = fmaxf(m, __shfl_xor_sync(0xffffffffu, m, off));
    if (lane == 0) sm[w] = m;
    __syncthreads();
    if (w == 0) {
        float t = sm[lane];
        #pragma unroll
        for (int off = 16; off; off >>= 1) t = fmaxf(t, __shfl_xor_sync(0xffffffffu, t, off));
        if (lane == 0) sm[0] = t;
    }
    __syncthreads();
    float MX = sm[0];
    __syncthreads();

    float se = expf(v0 - MX) + expf(v1 - MX);
    #pragma unroll
    for (int off = 16; off; off >>= 1) se += __shfl_xor_sync(0xffffffffu, se, off);
    if (lane == 0) sm[w] = se;
    __syncthreads();
    if (w == 0) {
        float t = sm[lane];
        #pragma unroll
        for (int off = 16; off; off >>= 1) t += __shfl_xor_sync(0xffffffffu, t, off);
        if (lane == 0) sm[0] = logf(t);
    }
    __syncthreads();
    float LS = sm[0];
    out[(size_t)b * NT + tid] = v0 - MX - LS;
    out[(size_t)b * NT + tid + 1024] = v1 - MX - LS;
}

// ---------------- launch ----------------
extern "C" void kernel_launch(void* const* d_in, const int* in_sizes, int n_in,
                              void* d_out, int out_size) {
    const float* x  = (const float*)d_in[0];
    const float* wg = (const float*)d_in[1];
    const float* w1 = (const float*)d_in[2];
    const float* b1 = (const float*)d_in[3];
    const float* w2 = (const float*)d_in[4];
    const float* b2 = (const float*)d_in[5];
    float* out = (float*)d_out;
    (void)in_sizes; (void)n_in; (void)out_size;

    cudaFuncSetAttribute(expert_gemm_imma,
                         cudaFuncAttributeMaxDynamicSharedMemorySize, SMEM_DYN);

    router_quant<<<NS, 256>>>(x, wg);
    colmax_w1<<<dim3(NH / 256, NE), 256>>>(w1);
    transpose_quant_w1<<<dim3(NM / 32, NH / 32, NE), dim3(32, 8)>>>(w1);
    w2b2sum_kernel<<<NE * NH / 8 + 1, 256>>>(w2, b2);
    build_kernel<<<NE, 1024>>>();
    expert_gemm_imma<<<dim3(NC / BM, NH / BN, NE), 256, SMEM_DYN>>>(b1);
    logsoftmax_kernel<<<NB, 1024>>>(out);
}